// round 9
// baseline (speedup 1.0000x reference)
#include <cuda_runtime.h>
#include <cfloat>

#define BATCH 4
#define M 4096
#define TX 128
#define NW (TX / 32)            // 4 warps
#define R 4                     // x-points per thread
#define XPB (TX * R)            // 512 x per block
#define XT (M / XPB)            // 8 x-tiles
#define YC 32                   // y-chunks
#define YCHUNK (M / YC)         // 128 y per chunk
#define NBLK (BATCH * XT * YC)  // 1024 blocks

// Order-preserving min-keys: key = ~float_bits(d^2), d^2 >= 0.
// Larger key == smaller d^2; all real keys > 0, so zero-init is the identity
// for atomicMax. The fused tail resets entries to 0 after consuming them,
// so every graph replay starts from the identity state.
__device__ unsigned int g_rowkey[BATCH * M];  // [b][x]  min over all y
__device__ unsigned int g_colkey[BATCH * M];  // [b][y]  min over all x
__device__ unsigned int g_count;              // self-resetting done counter

__global__ __launch_bounds__(TX) void chamfer_fused(const float* __restrict__ x,
                                                    const float* __restrict__ y,
                                                    float* __restrict__ out) {
    __shared__ float4 sy[2 * YCHUNK];        // y chunk doubled: linear index
    __shared__ float scol[NW][2 * YCHUNK];   // per-warp col-min, doubled
    __shared__ bool s_last;

    int bid = blockIdx.x;
    int yc = bid & (YC - 1);
    int xt = (bid >> 5) & (XT - 1);
    int b  = bid >> 8;

    int tid = threadIdx.x;
    int lane = tid & 31;
    int w = tid >> 5;

    // load y chunk (duplicated so sy[lane+k] needs no mask), precompute |p|^2
    const float* ysrc = y + ((size_t)b * M + yc * YCHUNK) * 3;
    if (tid < YCHUNK) {
        float p0 = ysrc[tid * 3 + 0];
        float p1 = ysrc[tid * 3 + 1];
        float p2 = ysrc[tid * 3 + 2];
        float4 v = make_float4(p0, p1, p2, fmaf(p0, p0, fmaf(p1, p1, p2 * p2)));
        sy[tid] = v;
        sy[tid + YCHUNK] = v;
    }
#pragma unroll
    for (int i = 0; i < NW * 2 * YCHUNK / TX; i++)
        ((float*)scol)[i * TX + tid] = FLT_MAX;

    // my R x-points -> registers
    float n0[R], n1[R], n2[R], sx[R], rmin[R];
    const float* xsrc = x + ((size_t)b * M + xt * XPB) * 3;
#pragma unroll
    for (int r = 0; r < R; r++) {
        int xi = tid + r * TX;
        float a0 = xsrc[xi * 3 + 0];
        float a1 = xsrc[xi * 3 + 1];
        float a2 = xsrc[xi * 3 + 2];
        sx[r] = fmaf(a0, a0, fmaf(a1, a1, a2 * a2));
        n0[r] = -2.0f * a0;
        n1[r] = -2.0f * a1;
        n2[r] = -2.0f * a2;
        rmin[r] = FLT_MAX;
    }
    __syncthreads();

    // volatile pins LDS/STS order: lane-staggered linear index gives distinct
    // addresses within each step; an address written by lane l+1 at step k is
    // re-read by lane l at step k+1 — same warp, program order through LSU.
    volatile float* sc = scol[w] + lane;
    const float4* syp = sy + lane;

#pragma unroll 8
    for (int k = 0; k < YCHUNK; k++) {
        float4 p = syp[k];
        float d0 = sx[0] + fmaf(n0[0], p.x, fmaf(n1[0], p.y, fmaf(n2[0], p.z, p.w)));
        float d1 = sx[1] + fmaf(n0[1], p.x, fmaf(n1[1], p.y, fmaf(n2[1], p.z, p.w)));
        float d2 = sx[2] + fmaf(n0[2], p.x, fmaf(n1[2], p.y, fmaf(n2[2], p.z, p.w)));
        float d3 = sx[3] + fmaf(n0[3], p.x, fmaf(n1[3], p.y, fmaf(n2[3], p.z, p.w)));
        rmin[0] = fminf(rmin[0], d0);
        rmin[1] = fminf(rmin[1], d1);
        rmin[2] = fminf(rmin[2], d2);
        rmin[3] = fminf(rmin[3], d3);
        float c = fminf(fminf(d0, d1), fminf(d2, d3));
        sc[k] = fminf(sc[k], c);
    }

    // rows: fold via order-preserving atomicMax key
#pragma unroll
    for (int r = 0; r < R; r++) {
        unsigned int key = ~__float_as_uint(fmaxf(rmin[r], 0.0f));
        atomicMax(&g_rowkey[(size_t)b * M + xt * XPB + tid + r * TX], key);
    }

    __syncthreads();

    // merge doubled halves + warps, fold cols via atomicMax key
    if (tid < YCHUNK) {
        float v = FLT_MAX;
#pragma unroll
        for (int i = 0; i < NW; i++)
            v = fminf(v, fminf(scol[i][tid], scol[i][tid + YCHUNK]));
        unsigned int key = ~__float_as_uint(fmaxf(v, 0.0f));
        atomicMax(&g_colkey[(size_t)b * M + yc * YCHUNK + tid], key);
    }

    // ---- fused final reduce: last block to finish folds everything ----
    if (tid == 0) {
        __threadfence();  // release: my atomicMax results visible
        s_last = (atomicAdd(&g_count, 1u) == NBLK - 1);
    }
    __syncthreads();
    if (!s_last) return;

    __threadfence();  // acquire: all blocks' atomicMax results visible

    // warp w handles batch w; each lane sums 128 row + 128 col keys in a
    // fixed order -> deterministic. Keys reset to 0 for the next replay.
    {
        int bb = w;
        float s = 0.0f;
#pragma unroll 4
        for (int i = 0; i < M / 32; i++) {
            size_t idx = (size_t)bb * M + lane + 32 * i;
            unsigned int kr = g_rowkey[idx];
            g_rowkey[idx] = 0u;
            s += sqrtf(__uint_as_float(~kr));
            unsigned int kc = g_colkey[idx];
            g_colkey[idx] = 0u;
            s += sqrtf(__uint_as_float(~kc));
        }
        for (int o = 16; o; o >>= 1) s += __shfl_down_sync(0xffffffffu, s, o);
        if (lane == 0) out[bb] = s * (1.0f / (float)M);
    }
    if (tid == 0) g_count = 0;  // reset for next graph replay
}

extern "C" void kernel_launch(void* const* d_in, const int* in_sizes, int n_in,
                              void* d_out, int out_size) {
    const float* x = (const float*)d_in[0];
    const float* y = (const float*)d_in[1];
    float* out = (float*)d_out;

    chamfer_fused<<<NBLK, TX>>>(x, y, out);
}

// round 10
// speedup vs baseline: 3.1527x; 3.1527x over previous
#include <cuda_runtime.h>
#include <cfloat>

#define BATCH 4
#define M 4096
#define TX 128
#define NW (TX / 32)            // 4 warps
#define R 4                     // x-points per thread
#define XPB (TX * R)            // 512 x per block
#define XT (M / XPB)            // 8 x-tiles
#define YC 32                   // y-chunks
#define YCHUNK (M / YC)         // 128 y per chunk
#define NBLK (BATCH * XT * YC)  // 1024 blocks
#define NRED 16                 // reduce blocks
#define KPB (2 * BATCH * M / NRED)  // 2048 keys per reduce block

// Order-preserving min-keys: key = ~float_bits(d^2), d^2 >= 0.
// Larger key == smaller d^2; all real keys > 0, so zero-init is the identity
// for atomicMax. chamfer_reduce resets entries to 0 after consuming them,
// so every graph replay starts from the identity state.
__device__ unsigned int g_rowkey[BATCH * M];  // [b][x]  min over all y
__device__ unsigned int g_colkey[BATCH * M];  // [b][y]  min over all x
__device__ float g_sums[NRED];
__device__ unsigned int g_count;              // self-resetting done counter

__global__ __launch_bounds__(TX) void chamfer_main(const float* __restrict__ x,
                                                   const float* __restrict__ y) {
    __shared__ float4 sy[2 * YCHUNK];        // y chunk doubled: linear index
    __shared__ float scol[NW][2 * YCHUNK];   // per-warp col-min, doubled

    int bid = blockIdx.x;
    int yc = bid & (YC - 1);
    int xt = (bid >> 5) & (XT - 1);
    int b  = bid >> 8;

    int tid = threadIdx.x;
    int lane = tid & 31;
    int w = tid >> 5;

    // load y chunk (duplicated so sy[lane+k] needs no mask), precompute |p|^2
    const float* ysrc = y + ((size_t)b * M + yc * YCHUNK) * 3;
    if (tid < YCHUNK) {
        float p0 = ysrc[tid * 3 + 0];
        float p1 = ysrc[tid * 3 + 1];
        float p2 = ysrc[tid * 3 + 2];
        float4 v = make_float4(p0, p1, p2, fmaf(p0, p0, fmaf(p1, p1, p2 * p2)));
        sy[tid] = v;
        sy[tid + YCHUNK] = v;
    }
#pragma unroll
    for (int i = 0; i < NW * 2 * YCHUNK / TX; i++)
        ((float*)scol)[i * TX + tid] = FLT_MAX;

    // my R x-points -> registers
    float n0[R], n1[R], n2[R], sx[R], rmin[R];
    const float* xsrc = x + ((size_t)b * M + xt * XPB) * 3;
#pragma unroll
    for (int r = 0; r < R; r++) {
        int xi = tid + r * TX;
        float a0 = xsrc[xi * 3 + 0];
        float a1 = xsrc[xi * 3 + 1];
        float a2 = xsrc[xi * 3 + 2];
        sx[r] = fmaf(a0, a0, fmaf(a1, a1, a2 * a2));
        n0[r] = -2.0f * a0;
        n1[r] = -2.0f * a1;
        n2[r] = -2.0f * a2;
        rmin[r] = FLT_MAX;
    }
    __syncthreads();

    // volatile pins LDS/STS order: lane-staggered linear index gives distinct
    // addresses within each step; an address written by lane l+1 at step k is
    // re-read by lane l at step k+1 — same warp, program order through LSU.
    volatile float* sc = scol[w] + lane;
    const float4* syp = sy + lane;

#pragma unroll 8
    for (int k = 0; k < YCHUNK; k++) {
        float4 p = syp[k];
        float d0 = sx[0] + fmaf(n0[0], p.x, fmaf(n1[0], p.y, fmaf(n2[0], p.z, p.w)));
        float d1 = sx[1] + fmaf(n0[1], p.x, fmaf(n1[1], p.y, fmaf(n2[1], p.z, p.w)));
        float d2 = sx[2] + fmaf(n0[2], p.x, fmaf(n1[2], p.y, fmaf(n2[2], p.z, p.w)));
        float d3 = sx[3] + fmaf(n0[3], p.x, fmaf(n1[3], p.y, fmaf(n2[3], p.z, p.w)));
        rmin[0] = fminf(rmin[0], d0);
        rmin[1] = fminf(rmin[1], d1);
        rmin[2] = fminf(rmin[2], d2);
        rmin[3] = fminf(rmin[3], d3);
        float c = fminf(fminf(d0, d1), fminf(d2, d3));
        sc[k] = fminf(sc[k], c);
    }

    // rows: fold via order-preserving atomicMax key
#pragma unroll
    for (int r = 0; r < R; r++) {
        unsigned int key = ~__float_as_uint(fmaxf(rmin[r], 0.0f));
        atomicMax(&g_rowkey[(size_t)b * M + xt * XPB + tid + r * TX], key);
    }

    __syncthreads();

    // merge doubled halves + warps, fold cols via atomicMax key
    if (tid < YCHUNK) {
        float v = FLT_MAX;
#pragma unroll
        for (int i = 0; i < NW; i++)
            v = fminf(v, fminf(scol[i][tid], scol[i][tid + YCHUNK]));
        unsigned int key = ~__float_as_uint(fmaxf(v, 0.0f));
        atomicMax(&g_colkey[(size_t)b * M + yc * YCHUNK + tid], key);
    }
}

// 16 blocks x 256 threads, 2048 contiguous keys each (8 per thread,
// coalesced). Blocks 0-7: g_rowkey (2 blocks per batch), 8-15: g_colkey.
// Keys reset to 0 after reading (identity for next replay). Last block
// folds the 16 partials into out in a fixed order (deterministic).
__global__ __launch_bounds__(256) void chamfer_reduce(float* __restrict__ out) {
    int blk = blockIdx.x;
    int tid = threadIdx.x;
    unsigned int* base = (blk < 8) ? (g_rowkey + blk * KPB)
                                   : (g_colkey + (blk - 8) * KPB);
    float sum = 0.0f;
#pragma unroll
    for (int r = 0; r < KPB / 256; r++) {
        unsigned int k = base[r * 256 + tid];
        base[r * 256 + tid] = 0u;
        sum += sqrtf(__uint_as_float(~k));
    }

    __shared__ float red[8];
    for (int o = 16; o; o >>= 1) sum += __shfl_down_sync(0xffffffffu, sum, o);
    if ((tid & 31) == 0) red[tid >> 5] = sum;
    __syncthreads();
    if (tid == 0) {
        float s = 0.0f;
#pragma unroll
        for (int i = 0; i < 8; i++) s += red[i];
        g_sums[blk] = s;
        __threadfence();
        unsigned int n = atomicAdd(&g_count, 1u);
        if (n == NRED - 1) {
            __threadfence();
#pragma unroll
            for (int bb = 0; bb < BATCH; bb++) {
                float t = g_sums[bb * 2] + g_sums[bb * 2 + 1] +
                          g_sums[8 + bb * 2] + g_sums[8 + bb * 2 + 1];
                out[bb] = t * (1.0f / (float)M);
            }
            g_count = 0;  // reset for next graph replay
        }
    }
}

extern "C" void kernel_launch(void* const* d_in, const int* in_sizes, int n_in,
                              void* d_out, int out_size) {
    const float* x = (const float*)d_in[0];
    const float* y = (const float*)d_in[1];
    float* out = (float*)d_out;

    chamfer_main<<<NBLK, TX>>>(x, y);
    chamfer_reduce<<<NRED, 256>>>(out);
}

// round 11
// speedup vs baseline: 3.3315x; 1.0567x over previous
#include <cuda_runtime.h>
#include <cfloat>

#define BATCH 4
#define M 4096
#define TX 128
#define NW (TX / 32)            // 4 warps
#define R 4                     // x-points per thread
#define XPB (TX * R)            // 512 x per block
#define XT (M / XPB)            // 8 x-tiles
#define YC 32                   // y-chunks
#define YCHUNK (M / YC)         // 128 y per chunk
#define NBLK (BATCH * XT * YC)  // 1024 blocks

// Order-preserving min-keys: key = ~float_bits(d^2), d^2 >= 0.
// Larger key == smaller d^2; all real keys > 0, so zero-init is the identity
// for atomicMax. chamfer_reduce resets entries to 0 after consuming them,
// so every graph replay starts from the identity state.
__device__ unsigned int g_rowkey[BATCH * M];  // [b][x]  min over all y
__device__ unsigned int g_colkey[BATCH * M];  // [b][y]  min over all x

__global__ __launch_bounds__(TX) void chamfer_main(const float* __restrict__ x,
                                                   const float* __restrict__ y) {
    __shared__ float4 sy[2 * YCHUNK];        // y chunk doubled: linear index
    __shared__ float scol[NW][2 * YCHUNK];   // per-warp col-min, doubled

    int bid = blockIdx.x;
    int yc = bid & (YC - 1);
    int xt = (bid >> 5) & (XT - 1);
    int b  = bid >> 8;

    int tid = threadIdx.x;
    int lane = tid & 31;
    int w = tid >> 5;

    // load y chunk (duplicated so sy[lane+k] needs no mask), precompute |p|^2
    const float* ysrc = y + ((size_t)b * M + yc * YCHUNK) * 3;
    if (tid < YCHUNK) {
        float p0 = ysrc[tid * 3 + 0];
        float p1 = ysrc[tid * 3 + 1];
        float p2 = ysrc[tid * 3 + 2];
        float4 v = make_float4(p0, p1, p2, fmaf(p0, p0, fmaf(p1, p1, p2 * p2)));
        sy[tid] = v;
        sy[tid + YCHUNK] = v;
    }
#pragma unroll
    for (int i = 0; i < NW * 2 * YCHUNK / TX; i++)
        ((float*)scol)[i * TX + tid] = FLT_MAX;

    // my R x-points -> registers
    float n0[R], n1[R], n2[R], sx[R], rmin[R];
    const float* xsrc = x + ((size_t)b * M + xt * XPB) * 3;
#pragma unroll
    for (int r = 0; r < R; r++) {
        int xi = tid + r * TX;
        float a0 = xsrc[xi * 3 + 0];
        float a1 = xsrc[xi * 3 + 1];
        float a2 = xsrc[xi * 3 + 2];
        sx[r] = fmaf(a0, a0, fmaf(a1, a1, a2 * a2));
        n0[r] = -2.0f * a0;
        n1[r] = -2.0f * a1;
        n2[r] = -2.0f * a2;
        rmin[r] = FLT_MAX;
    }
    __syncthreads();

    // volatile pins LDS/STS order: lane-staggered linear index gives distinct
    // addresses within each step; an address written by lane l+1 at step k is
    // re-read by lane l at step k+1 — same warp, program order through LSU.
    volatile float* sc = scol[w] + lane;
    const float4* syp = sy + lane;

#pragma unroll 8
    for (int k = 0; k < YCHUNK; k++) {
        float4 p = syp[k];
        float d0 = sx[0] + fmaf(n0[0], p.x, fmaf(n1[0], p.y, fmaf(n2[0], p.z, p.w)));
        float d1 = sx[1] + fmaf(n0[1], p.x, fmaf(n1[1], p.y, fmaf(n2[1], p.z, p.w)));
        float d2 = sx[2] + fmaf(n0[2], p.x, fmaf(n1[2], p.y, fmaf(n2[2], p.z, p.w)));
        float d3 = sx[3] + fmaf(n0[3], p.x, fmaf(n1[3], p.y, fmaf(n2[3], p.z, p.w)));
        rmin[0] = fminf(rmin[0], d0);
        rmin[1] = fminf(rmin[1], d1);
        rmin[2] = fminf(rmin[2], d2);
        rmin[3] = fminf(rmin[3], d3);
        float c = fminf(fminf(d0, d1), fminf(d2, d3));
        sc[k] = fminf(sc[k], c);
    }

    // rows: fold via order-preserving atomicMax key
#pragma unroll
    for (int r = 0; r < R; r++) {
        unsigned int key = ~__float_as_uint(fmaxf(rmin[r], 0.0f));
        atomicMax(&g_rowkey[(size_t)b * M + xt * XPB + tid + r * TX], key);
    }

    __syncthreads();

    // merge doubled halves + warps, fold cols via atomicMax key
    if (tid < YCHUNK) {
        float v = FLT_MAX;
#pragma unroll
        for (int i = 0; i < NW; i++)
            v = fminf(v, fminf(scol[i][tid], scol[i][tid + YCHUNK]));
        unsigned int key = ~__float_as_uint(fmaxf(v, 0.0f));
        atomicMax(&g_colkey[(size_t)b * M + yc * YCHUNK + tid], key);
    }
}

// 4 blocks, one per batch: read 4096 row + 4096 col keys as uint4 (8 vec
// loads / 32 keys per thread, coalesced), sqrt-sum, reset keys to 0, write
// out[b] directly. No done-counter, no second phase. Deterministic: fixed
// per-thread accumulation order + fixed-order block reduction.
__global__ __launch_bounds__(256) void chamfer_reduce(float* __restrict__ out) {
    int b   = blockIdx.x;
    int tid = threadIdx.x;
    float sum = 0.0f;

    uint4* rbase = (uint4*)(g_rowkey + (size_t)b * M);
    uint4* cbase = (uint4*)(g_colkey + (size_t)b * M);
    const uint4 zero4 = make_uint4(0u, 0u, 0u, 0u);

#pragma unroll
    for (int r = 0; r < M / 4 / 256; r++) {   // 4 iterations
        uint4 kr = rbase[r * 256 + tid];
        rbase[r * 256 + tid] = zero4;
        sum += sqrtf(__uint_as_float(~kr.x)) + sqrtf(__uint_as_float(~kr.y)) +
               sqrtf(__uint_as_float(~kr.z)) + sqrtf(__uint_as_float(~kr.w));
        uint4 kc = cbase[r * 256 + tid];
        cbase[r * 256 + tid] = zero4;
        sum += sqrtf(__uint_as_float(~kc.x)) + sqrtf(__uint_as_float(~kc.y)) +
               sqrtf(__uint_as_float(~kc.z)) + sqrtf(__uint_as_float(~kc.w));
    }

    __shared__ float red[8];
    for (int o = 16; o; o >>= 1) sum += __shfl_down_sync(0xffffffffu, sum, o);
    if ((tid & 31) == 0) red[tid >> 5] = sum;
    __syncthreads();
    if (tid == 0) {
        float s = 0.0f;
#pragma unroll
        for (int i = 0; i < 8; i++) s += red[i];
        out[b] = s * (1.0f / (float)M);
    }
}

extern "C" void kernel_launch(void* const* d_in, const int* in_sizes, int n_in,
                              void* d_out, int out_size) {
    const float* x = (const float*)d_in[0];
    const float* y = (const float*)d_in[1];
    float* out = (float*)d_out;

    chamfer_main<<<NBLK, TX>>>(x, y);
    chamfer_reduce<<<BATCH, 256>>>(out);
}

// round 13
// speedup vs baseline: 3.3869x; 1.0166x over previous
#include <cuda_runtime.h>
#include <cfloat>

#define BATCH 4
#define M 4096
#define TX 128
#define NW (TX / 32)            // 4 warps
#define R 4                     // x-points per thread
#define XPB (TX * R)            // 512 x per block
#define XT (M / XPB)            // 8 x-tiles
#define YC 32                   // y-chunks
#define YCHUNK (M / YC)         // 128 y per chunk
#define NBLK (BATCH * XT * YC)  // 1024 blocks

// Order-preserving min-keys: key = ~float_bits(d^2), d^2 >= 0.
// Larger key == smaller d^2; all real keys > 0, so zero-init is the identity
// for atomicMax. chamfer_reduce resets entries to 0 after consuming them,
// so every graph replay starts from the identity state.
__device__ unsigned int g_rowkey[BATCH * M];  // [b][x]  min over all y
__device__ unsigned int g_colkey[BATCH * M];  // [b][y]  min over all x

__global__ __launch_bounds__(TX) void chamfer_main(const float* __restrict__ x,
                                                   const float* __restrict__ y) {
    __shared__ float4 sy[2 * YCHUNK];        // y chunk doubled: linear index
    __shared__ float scol[NW][2 * YCHUNK];   // per-warp col-min, doubled

    int bid = blockIdx.x;
    int yc = bid & (YC - 1);
    int xt = (bid >> 5) & (XT - 1);
    int b  = bid >> 8;

    int tid = threadIdx.x;
    int lane = tid & 31;
    int w = tid >> 5;

    // load y chunk (duplicated so sy[lane+k] needs no mask), precompute |p|^2
    const float* ysrc = y + ((size_t)b * M + yc * YCHUNK) * 3;
    if (tid < YCHUNK) {
        float p0 = ysrc[tid * 3 + 0];
        float p1 = ysrc[tid * 3 + 1];
        float p2 = ysrc[tid * 3 + 2];
        float4 v = make_float4(p0, p1, p2, fmaf(p0, p0, fmaf(p1, p1, p2 * p2)));
        sy[tid] = v;
        sy[tid + YCHUNK] = v;
    }
#pragma unroll
    for (int i = 0; i < NW * 2 * YCHUNK / TX; i++)
        ((float*)scol)[i * TX + tid] = FLT_MAX;

    // my R x-points -> registers
    float n0[R], n1[R], n2[R], sx[R], rmin[R];
    const float* xsrc = x + ((size_t)b * M + xt * XPB) * 3;
#pragma unroll
    for (int r = 0; r < R; r++) {
        int xi = tid + r * TX;
        float a0 = xsrc[xi * 3 + 0];
        float a1 = xsrc[xi * 3 + 1];
        float a2 = xsrc[xi * 3 + 2];
        sx[r] = fmaf(a0, a0, fmaf(a1, a1, a2 * a2));
        n0[r] = -2.0f * a0;
        n1[r] = -2.0f * a1;
        n2[r] = -2.0f * a2;
        rmin[r] = FLT_MAX;
    }
    __syncthreads();

    // volatile pins LDS/STS order: lane-staggered linear index gives distinct
    // addresses within each step; an address written by lane l+1 at step k is
    // re-read by lane l at step k+1 — same warp, program order through LSU.
    volatile float* sc = scol[w] + lane;
    const float4* syp = sy + lane;

#pragma unroll 8
    for (int k = 0; k < YCHUNK; k++) {
        float4 p = syp[k];
        float d0 = sx[0] + fmaf(n0[0], p.x, fmaf(n1[0], p.y, fmaf(n2[0], p.z, p.w)));
        float d1 = sx[1] + fmaf(n0[1], p.x, fmaf(n1[1], p.y, fmaf(n2[1], p.z, p.w)));
        float d2 = sx[2] + fmaf(n0[2], p.x, fmaf(n1[2], p.y, fmaf(n2[2], p.z, p.w)));
        float d3 = sx[3] + fmaf(n0[3], p.x, fmaf(n1[3], p.y, fmaf(n2[3], p.z, p.w)));
        rmin[0] = fminf(rmin[0], d0);
        rmin[1] = fminf(rmin[1], d1);
        rmin[2] = fminf(rmin[2], d2);
        rmin[3] = fminf(rmin[3], d3);
        float c = fminf(fminf(d0, d1), fminf(d2, d3));
        sc[k] = fminf(sc[k], c);
    }

    // rows: fold via order-preserving atomicMax key
#pragma unroll
    for (int r = 0; r < R; r++) {
        unsigned int key = ~__float_as_uint(fmaxf(rmin[r], 0.0f));
        atomicMax(&g_rowkey[(size_t)b * M + xt * XPB + tid + r * TX], key);
    }

    __syncthreads();

    // merge doubled halves + warps, fold cols via atomicMax key
    if (tid < YCHUNK) {
        float v = FLT_MAX;
#pragma unroll
        for (int i = 0; i < NW; i++)
            v = fminf(v, fminf(scol[i][tid], scol[i][tid + YCHUNK]));
        unsigned int key = ~__float_as_uint(fmaxf(v, 0.0f));
        atomicMax(&g_colkey[(size_t)b * M + yc * YCHUNK + tid], key);
    }
}

// 4 blocks, one per batch. PDL secondary: launched with programmatic stream
// serialization, its blocks come up and spin in cudaGridDependencySynchronize
// while chamfer_main's tail wave still runs, then execute immediately on
// main's completion (implicit trigger at primary exit). Reads 4096 row +
// 4096 col keys as uint4 (coalesced), sqrt-sums, resets keys to 0, writes
// out[b] directly. Deterministic: fixed accumulation and reduction order.
__global__ __launch_bounds__(256) void chamfer_reduce(float* __restrict__ out) {
    cudaGridDependencySynchronize();

    int b   = blockIdx.x;
    int tid = threadIdx.x;
    float sum = 0.0f;

    uint4* rbase = (uint4*)(g_rowkey + (size_t)b * M);
    uint4* cbase = (uint4*)(g_colkey + (size_t)b * M);
    const uint4 zero4 = make_uint4(0u, 0u, 0u, 0u);

#pragma unroll
    for (int r = 0; r < M / 4 / 256; r++) {   // 4 iterations
        uint4 kr = rbase[r * 256 + tid];
        rbase[r * 256 + tid] = zero4;
        sum += sqrtf(__uint_as_float(~kr.x)) + sqrtf(__uint_as_float(~kr.y)) +
               sqrtf(__uint_as_float(~kr.z)) + sqrtf(__uint_as_float(~kr.w));
        uint4 kc = cbase[r * 256 + tid];
        cbase[r * 256 + tid] = zero4;
        sum += sqrtf(__uint_as_float(~kc.x)) + sqrtf(__uint_as_float(~kc.y)) +
               sqrtf(__uint_as_float(~kc.z)) + sqrtf(__uint_as_float(~kc.w));
    }

    __shared__ float red[8];
    for (int o = 16; o; o >>= 1) sum += __shfl_down_sync(0xffffffffu, sum, o);
    if ((tid & 31) == 0) red[tid >> 5] = sum;
    __syncthreads();
    if (tid == 0) {
        float s = 0.0f;
#pragma unroll
        for (int i = 0; i < 8; i++) s += red[i];
        out[b] = s * (1.0f / (float)M);
    }
}

extern "C" void kernel_launch(void* const* d_in, const int* in_sizes, int n_in,
                              void* d_out, int out_size) {
    const float* x = (const float*)d_in[0];
    const float* y = (const float*)d_in[1];
    float* out = (float*)d_out;

    chamfer_main<<<NBLK, TX>>>(x, y);

    // Secondary launch with programmatic stream serialization (PDL): may
    // begin scheduling before chamfer_main completes; correctness is
    // guaranteed by cudaGridDependencySynchronize() inside the kernel.
    cudaLaunchConfig_t cfg = {};
    cfg.gridDim = dim3(BATCH, 1, 1);
    cfg.blockDim = dim3(256, 1, 1);
    cfg.dynamicSmemBytes = 0;
    cfg.stream = 0;
    cudaLaunchAttribute attr[1];
    attr[0].id = cudaLaunchAttributeProgrammaticStreamSerialization;
    attr[0].val.programmaticStreamSerializationAllowed = 1;
    cfg.attrs = attr;
    cfg.numAttrs = 1;
    cudaLaunchKernelEx(&cfg, chamfer_reduce, out);
}